// round 8
// baseline (speedup 1.0000x reference)
#include <cuda_runtime.h>
#include <cuda_bf16.h>

#define BB 512
#define LL 2048
#define CC 64
#define START_S 62
#define STOP_S 63

// scratch (no cudaMalloc allowed)
__device__ unsigned g_eTbf[CC * 32];  // [cp][k2] = bf16x2{ exp(T[2k2][cp]), exp(T[2k2+1][cp]) }
__device__ float g_eTstop[CC];        // exp(T[c][STOP])
__device__ float g_trow_start[CC];    // T[START][c]
__device__ float g_part[BB];
__device__ float g_scores[BB];

// bf16x2 packed ops
__device__ __forceinline__ unsigned bffma(unsigned a, unsigned b, unsigned c) {
    unsigned d;
    asm("fma.rn.bf16x2 %0, %1, %2, %3;" : "=r"(d) : "r"(a), "r"(b), "r"(c));
    return d;
}
__device__ __forceinline__ unsigned bfadd(unsigned a, unsigned b) {
    unsigned d;
    asm("add.rn.bf16x2 %0, %1, %2;" : "=r"(d) : "r"(a), "r"(b));
    return d;
}
// sum both bf16 lanes into fp32 (bf16 -> fp32 is a 16-bit shift)
__device__ __forceinline__ float bfsum(unsigned ab) {
    float lo = __uint_as_float(ab << 16);
    float hi = __uint_as_float(ab & 0xffff0000u);
    return lo + hi;
}

// ---------------------------------------------------------------------------
// Precompute bf16x2-packed exp(T) + fp32 boundary vectors.
// ---------------------------------------------------------------------------
__global__ void prep_kernel(const float* __restrict__ T) {
    int i = blockIdx.x * blockDim.x + threadIdx.x;
    if (i < CC * 32) {
        int cp = i >> 5;
        int k2 = i & 31;
        __nv_bfloat162 p = __floats2bfloat162_rn(__expf(T[(2 * k2) * CC + cp]),
                                                 __expf(T[(2 * k2 + 1) * CC + cp]));
        g_eTbf[i] = *reinterpret_cast<unsigned*>(&p);
    }
    if (i < CC) {
        g_eTstop[i]     = __expf(T[i * CC + STOP_S]);
        g_trow_start[i] = T[START_S * CC + i];
    }
}

// two independent 64-dots in bf16x2, interleaved for ILP
__device__ __forceinline__ void dotbf2(const unsigned* __restrict__ va,
                                       const unsigned* __restrict__ vb,
                                       const unsigned* __restrict__ eT,
                                       float& ra, float& rb) {
    const uint4* qa = reinterpret_cast<const uint4*>(va);
    const uint4* qb = reinterpret_cast<const uint4*>(vb);
    unsigned a0 = 0, a1 = 0, a2 = 0, a3 = 0;
    unsigned b0 = 0, b1 = 0, b2 = 0, b3 = 0;
#pragma unroll
    for (int j = 0; j < 8; ++j) {
        uint4 x = qa[j];
        uint4 y = qb[j];
        a0 = bffma(x.x, eT[4 * j + 0], a0);
        b0 = bffma(y.x, eT[4 * j + 0], b0);
        a1 = bffma(x.y, eT[4 * j + 1], a1);
        b1 = bffma(y.y, eT[4 * j + 1], b1);
        a2 = bffma(x.z, eT[4 * j + 2], a2);
        b2 = bffma(y.z, eT[4 * j + 2], b2);
        a3 = bffma(x.w, eT[4 * j + 3], a3);
        b3 = bffma(y.w, eT[4 * j + 3], b3);
    }
    ra = bfsum(bfadd(bfadd(a0, a1), bfadd(a2, a3)));
    rb = bfsum(bfadd(bfadd(b0, b1), bfadd(b2, b3)));
}

// one forward step for BOTH batches. MODE: 0 plain, 1 launch warp-max, 2 renorm.
template <int MODE>
__device__ __forceinline__ void do_step2(float e0v, float m0v, float e1v, float m1v,
                                         float& v0, float& S0, float& v1, float& S1,
                                         int& cur,
                                         unsigned (*vsh)[2][32],   // [batch][buf][k2]
                                         float (*smaxb)[2],        // [batch][warp]
                                         int cp, int lane, int wid,
                                         const unsigned* __restrict__ eT) {
    if (MODE == 1) {            // warp-maxes of current v's — overlap the dots
        float x0 = v0, x1 = v1;
#pragma unroll
        for (int o = 16; o; o >>= 1) {
            x0 = fmaxf(x0, __shfl_xor_sync(0xffffffffu, x0, o));
            x1 = fmaxf(x1, __shfl_xor_sync(0xffffffffu, x1, o));
        }
        if (lane == 0) { smaxb[0][wid] = x0; smaxb[1][wid] = x1; }
    }
    float ee0 = __expf(e0v);
    float ee1 = __expf(e1v);
    float vr0 = v0, vr1 = v1;
    if (MODE == 2) {            // fold r = 1/max into emission factors
        float mm0 = fmaxf(smaxb[0][0], smaxb[0][1]);
        float mm1 = fmaxf(smaxb[1][0], smaxb[1][1]);
        float r0 = __fdividef(1.0f, mm0);
        float r1 = __fdividef(1.0f, mm1);
        S0 += __logf(mm0);
        S1 += __logf(mm1);
        ee0 *= r0; vr0 = v0 * r0;
        ee1 *= r1; vr1 = v1 * r1;
    }
    float a0, a1;
    dotbf2(vsh[0][cur], vsh[1][cur], eT, a0, a1);
    float nv0 = (m0v > 0.f) ? a0 * ee0 : vr0;
    float nv1 = (m1v > 0.f) ? a1 * ee1 : vr1;
    v0 = nv0; v1 = nv1;
    reinterpret_cast<__nv_bfloat16*>(vsh[0][cur ^ 1])[cp] = __float2bfloat16_rn(nv0);
    reinterpret_cast<__nv_bfloat16*>(vsh[1][cur ^ 1])[cp] = __float2bfloat16_rn(nv1);
    __syncthreads();
    cur ^= 1;
}

// ---------------------------------------------------------------------------
// Forward algorithm in exp-space, bf16 matvec, TWO batches per thread.
// One block (64 threads, 2 warps) handles batches (2*blk, 2*blk+1); thread cp
// owns state cp of both. The bf16x2 exp(T) column (32 regs) is shared by both
// recursions; their dots interleave to fill the latency shadow, and one
// barrier covers two batch-steps. Renorm every 4 steps, pipelined:
//   step 4k+1: launch warp-max shuffles (overlapping the dots)
//   step 4k+2: fold r = 1/max into the emission factors, S += log(max)
// Invariant per batch: alpha[c] = log(v[c]) + S.
// ---------------------------------------------------------------------------
__global__ void __launch_bounds__(CC) alpha_kernel(const float* __restrict__ em,
                                                   const float* __restrict__ mask) {
    const int b0   = blockIdx.x * 2;
    const int cp   = threadIdx.x;
    const int lane = cp & 31;
    const int wid  = cp >> 5;

    __shared__ __align__(16) unsigned vsh[2][2][32];  // [batch][buf][k2] bf16x2
    __shared__ float smaxb[2][2];
    __shared__ float ssum[2][2];

    // my packed exp(T) column: 32 bf16x2 regs (shared by both batches)
    unsigned eT[32];
    {
        const unsigned* g = g_eTbf + cp * 32;
#pragma unroll
        for (int k = 0; k < 32; ++k) eT[k] = g[k];
    }

    const float* emb0 = em + (size_t)b0 * (LL * CC);
    const float* emb1 = emb0 + (size_t)LL * CC;
    const float* mkb0 = mask + (size_t)b0 * LL;
    const float* mkb1 = mkb0 + LL;

    // t = 0
    float ts = g_trow_start[cp];
    float v0 = __expf(emb0[cp] + ts);
    float v1 = __expf(emb1[cp] + ts);
    float S0 = 0.0f, S1 = 0.0f;
    reinterpret_cast<__nv_bfloat16*>(vsh[0][0])[cp] = __float2bfloat16_rn(v0);
    reinterpret_cast<__nv_bfloat16*>(vsh[1][0])[cp] = __float2bfloat16_rn(v1);

    // prefetch pipeline, distance 3, both batches
    float ea0 = emb0[1 * CC + cp], ma0 = mkb0[1];
    float ea1 = emb1[1 * CC + cp], ma1 = mkb1[1];
    float eb0 = emb0[2 * CC + cp], mb0 = mkb0[2];
    float eb1 = emb1[2 * CC + cp], mb1 = mkb1[2];
    float ec0 = emb0[3 * CC + cp], mc0 = mkb0[3];
    float ec1 = emb1[3 * CC + cp], mc1 = mkb1[3];

    __syncthreads();

    int cur = 0;
#define ADVANCE(t_)                                                       \
    {                                                                     \
        int ti = (t_) + 3; if (ti > LL - 1) ti = LL - 1;                  \
        float en0 = emb0[(size_t)ti * CC + cp];                           \
        float en1 = emb1[(size_t)ti * CC + cp];                           \
        float mn0 = mkb0[ti];                                             \
        float mn1 = mkb1[ti];                                             \
        ea0 = eb0; ma0 = mb0; eb0 = ec0; mb0 = mc0; ec0 = en0; mc0 = mn0; \
        ea1 = eb1; ma1 = mb1; eb1 = ec1; mb1 = mc1; ec1 = en1; mc1 = mn1; \
    }

#pragma unroll 1
    for (int t = 1; t <= LL - 4; t += 4) {
        float x0 = ea0, y0 = ma0, x1 = ea1, y1 = ma1; ADVANCE(t);
        do_step2<1>(x0, y0, x1, y1, v0, S0, v1, S1, cur, vsh, smaxb, cp, lane, wid, eT);
        x0 = ea0; y0 = ma0; x1 = ea1; y1 = ma1; ADVANCE(t + 1);
        do_step2<2>(x0, y0, x1, y1, v0, S0, v1, S1, cur, vsh, smaxb, cp, lane, wid, eT);
        x0 = ea0; y0 = ma0; x1 = ea1; y1 = ma1; ADVANCE(t + 2);
        do_step2<0>(x0, y0, x1, y1, v0, S0, v1, S1, cur, vsh, smaxb, cp, lane, wid, eT);
        x0 = ea0; y0 = ma0; x1 = ea1; y1 = ma1; ADVANCE(t + 3);
        do_step2<0>(x0, y0, x1, y1, v0, S0, v1, S1, cur, vsh, smaxb, cp, lane, wid, eT);
    }
    // tail: t = 2045, 2046, 2047
#pragma unroll 1
    for (int t = LL - 3; t < LL; ++t) {
        float x0 = ea0, y0 = ma0, x1 = ea1, y1 = ma1; ADVANCE(t);
        do_step2<0>(x0, y0, x1, y1, v0, S0, v1, S1, cur, vsh, smaxb, cp, lane, wid, eT);
    }
#undef ADVANCE

    // partition_b = log( sum_c v[c] * exp(T[c,STOP]) ) + S   (fp32)
    float es = g_eTstop[cp];
    float t0 = v0 * es;
    float t1 = v1 * es;
#pragma unroll
    for (int o = 16; o; o >>= 1) {
        t0 += __shfl_xor_sync(0xffffffffu, t0, o);
        t1 += __shfl_xor_sync(0xffffffffu, t1, o);
    }
    if (lane == 0) { ssum[0][wid] = t0; ssum[1][wid] = t1; }
    __syncthreads();
    if (cp == 0) g_part[b0]     = __logf(ssum[0][0] + ssum[0][1]) + S0;
    if (cp == 1) g_part[b0 + 1] = __logf(ssum[1][0] + ssum[1][1]) + S1;
}

// ---------------------------------------------------------------------------
// Gold path score per batch (cheap gathers) — exact fp32.
// ---------------------------------------------------------------------------
__global__ void __launch_bounds__(256) scores_kernel(const float* __restrict__ em,
                                                     const float* __restrict__ T,
                                                     const float* __restrict__ mask,
                                                     const int* __restrict__ tags) {
    const int b   = blockIdx.x;
    const int tid = threadIdx.x;
    const float* emb = em + (size_t)b * (LL * CC);
    const float* mkb = mask + (size_t)b * LL;
    const int*   tgb = tags + (size_t)b * LL;

    float acc = 0.f, msum = 0.f;
    for (int t = tid; t < LL; t += 256) {
        msum += mkb[t];
        if (t >= 1) {
            int tg = tgb[t];
            int tq = tgb[t - 1];
            acc += (emb[(size_t)t * CC + tg] + T[tq * CC + tg]) * mkb[t];
        }
    }

    __shared__ float sacc[8], smsum[8];
#pragma unroll
    for (int o = 16; o; o >>= 1) {
        acc  += __shfl_xor_sync(0xffffffffu, acc, o);
        msum += __shfl_xor_sync(0xffffffffu, msum, o);
    }
    int lane = tid & 31, w = tid >> 5;
    if (lane == 0) { sacc[w] = acc; smsum[w] = msum; }
    __syncthreads();
    if (tid == 0) {
        float A = 0.f, M = 0.f;
#pragma unroll
        for (int i = 0; i < 8; ++i) { A += sacc[i]; M += smsum[i]; }
        int t0 = tgb[0];
        float s = A + emb[t0] + T[START_S * CC + t0];
        int last = (int)M - 1;               // mask sum of 1.0s is exact in fp32
        s += T[tgb[last] * CC + STOP_S];
        g_scores[b] = s;
    }
}

// ---------------------------------------------------------------------------
// mean(partition - scores)
// ---------------------------------------------------------------------------
__global__ void __launch_bounds__(512) finalize_kernel(float* __restrict__ out) {
    int tid = threadIdx.x;
    float d = g_part[tid] - g_scores[tid];
    __shared__ float sh[16];
#pragma unroll
    for (int o = 16; o; o >>= 1) d += __shfl_xor_sync(0xffffffffu, d, o);
    if ((tid & 31) == 0) sh[tid >> 5] = d;
    __syncthreads();
    if (tid < 16) {
        float x = sh[tid];
#pragma unroll
        for (int o = 8; o; o >>= 1) x += __shfl_xor_sync(0x0000ffffu, x, o);
        if (tid == 0) out[0] = x * (1.0f / BB);
    }
}

extern "C" void kernel_launch(void* const* d_in, const int* in_sizes, int n_in,
                              void* d_out, int out_size) {
    (void)in_sizes; (void)n_in; (void)out_size;
    const float* em   = (const float*)d_in[0];
    const float* T    = (const float*)d_in[1];
    const float* mask = (const float*)d_in[2];
    const int*   tags = (const int*)d_in[3];
    float* out = (float*)d_out;

    prep_kernel<<<4, 512>>>(T);
    alpha_kernel<<<BB / 2, CC>>>(em, mask);
    scores_kernel<<<BB, 256>>>(em, T, mask, tags);
    finalize_kernel<<<1, 512>>>(out);
}

// round 9
// speedup vs baseline: 1.5633x; 1.5633x over previous
#include <cuda_runtime.h>
#include <cuda_bf16.h>

#define BB 512
#define LL 2048
#define CC 64
#define START_S 62
#define STOP_S 63

// scratch (no cudaMalloc allowed)
__device__ unsigned g_eTbf[CC * 32];  // [cp][k2] = bf16x2{ exp(T[2k2][cp]), exp(T[2k2+1][cp]) }
__device__ float g_eTstop[CC];        // exp(T[c][STOP])
__device__ float g_trow_start[CC];    // T[START][c]
__device__ float g_part[BB];
__device__ float g_scores[BB];

// bf16x2 packed ops
__device__ __forceinline__ unsigned bffma(unsigned a, unsigned b, unsigned c) {
    unsigned d;
    asm("fma.rn.bf16x2 %0, %1, %2, %3;" : "=r"(d) : "r"(a), "r"(b), "r"(c));
    return d;
}
__device__ __forceinline__ unsigned bfadd(unsigned a, unsigned b) {
    unsigned d;
    asm("add.rn.bf16x2 %0, %1, %2;" : "=r"(d) : "r"(a), "r"(b));
    return d;
}
// sum both bf16 lanes into fp32 (bf16 -> fp32 is a 16-bit shift)
__device__ __forceinline__ float bfsum(unsigned ab) {
    float lo = __uint_as_float(ab << 16);
    float hi = __uint_as_float(ab & 0xffff0000u);
    return lo + hi;
}
// pack two fp32 into bf16x2: lo = x, hi = y
__device__ __forceinline__ unsigned bfpack(float x, float y) {
    unsigned d;
    asm("cvt.rn.bf16x2.f32 %0, %1, %2;" : "=r"(d) : "f"(y), "f"(x));
    return d;
}

// ---------------------------------------------------------------------------
// Precompute bf16x2-packed exp(T) + fp32 boundary vectors.
// ---------------------------------------------------------------------------
__global__ void prep_kernel(const float* __restrict__ T) {
    int i = blockIdx.x * blockDim.x + threadIdx.x;
    if (i < CC * 32) {
        int cp = i >> 5;
        int k2 = i & 31;
        __nv_bfloat162 p = __floats2bfloat162_rn(__expf(T[(2 * k2) * CC + cp]),
                                                 __expf(T[(2 * k2 + 1) * CC + cp]));
        g_eTbf[i] = *reinterpret_cast<unsigned*>(&p);
    }
    if (i < CC) {
        g_eTstop[i]     = __expf(T[i * CC + STOP_S]);
        g_trow_start[i] = T[START_S * CC + i];
    }
}

// two interleaved 64-dots in bf16x2 (output states 2*lane and 2*lane+1):
// 64 HFMA2 into 4+4 accumulators (depth 8), fp32 results.
__device__ __forceinline__ void dot2(const unsigned* __restrict__ vsh32,
                                     const unsigned* __restrict__ eA,
                                     const unsigned* __restrict__ eB,
                                     float& ra, float& rb) {
    const uint4* q = reinterpret_cast<const uint4*>(vsh32);
    unsigned a0 = 0, a1 = 0, a2 = 0, a3 = 0;
    unsigned b0 = 0, b1 = 0, b2 = 0, b3 = 0;
#pragma unroll
    for (int j = 0; j < 8; ++j) {
        uint4 x = q[j];
        a0 = bffma(x.x, eA[4 * j + 0], a0);
        b0 = bffma(x.x, eB[4 * j + 0], b0);
        a1 = bffma(x.y, eA[4 * j + 1], a1);
        b1 = bffma(x.y, eB[4 * j + 1], b1);
        a2 = bffma(x.z, eA[4 * j + 2], a2);
        b2 = bffma(x.z, eB[4 * j + 2], b2);
        a3 = bffma(x.w, eA[4 * j + 3], a3);
        b3 = bffma(x.w, eB[4 * j + 3], b3);
    }
    ra = bfsum(bfadd(bfadd(a0, a1), bfadd(a2, a3)));
    rb = bfsum(bfadd(bfadd(b0, b1), bfadd(b2, b3)));
}

// one forward step. MODE: 0 plain, 1 launch warp-max of v, 2 apply renorm.
// Single warp; the butterfly max leaves the result in ALL lanes (no smem).
template <int MODE>
__device__ __forceinline__ void do_step(float2 ev, float mkv,
                                        float& v0, float& v1, float& S, float& mx,
                                        int& cur, unsigned (*vsh)[32],
                                        const unsigned* __restrict__ eA,
                                        const unsigned* __restrict__ eB,
                                        int lane) {
    if (MODE == 1) {            // warp-max of current v — overlaps the dot
        float x = fmaxf(v0, v1);
#pragma unroll
        for (int o = 16; o; o >>= 1) x = fmaxf(x, __shfl_xor_sync(0xffffffffu, x, o));
        mx = x;
    }
    float ee0 = __expf(ev.x);
    float ee1 = __expf(ev.y);
    float vr0 = v0, vr1 = v1;
    if (MODE == 2) {            // fold r = 1/max into emission factors
        float r = __fdividef(1.0f, mx);
        S += __logf(mx);
        ee0 *= r; vr0 = v0 * r;
        ee1 *= r; vr1 = v1 * r;
    }
    float a, bq;
    dot2(vsh[cur], eA, eB, a, bq);
    float nv0 = (mkv > 0.f) ? a  * ee0 : vr0;
    float nv1 = (mkv > 0.f) ? bq * ee1 : vr1;
    v0 = nv0; v1 = nv1;
    vsh[cur ^ 1][lane] = bfpack(nv0, nv1);
    __syncwarp();
    cur ^= 1;
}

// ---------------------------------------------------------------------------
// Forward algorithm in exp-space. ONE 32-thread WARP per batch — no block
// barrier, no cross-warp traffic. Lane owns output states (2*lane, 2*lane+1);
// their bf16x2 exp(T) columns live in 64 registers; the two 32-HFMA2 dots
// interleave for ILP. v is exchanged as a 128-byte bf16x2 shared buffer
// (1 CVT + 1 STS.32 per lane, __syncwarp, 8 broadcast LDS.128 to read).
// Renorm every 4 steps: the shuffle butterfly (step 4k+1) overlaps the dot
// and leaves max in all lanes; step 4k+2 folds r = 1/max into the emission.
// Invariant: alpha[c] = log(v[c]) + S.
// ---------------------------------------------------------------------------
__global__ void __launch_bounds__(32) alpha_kernel(const float* __restrict__ em,
                                                   const float* __restrict__ mask) {
    const int b    = blockIdx.x;
    const int lane = threadIdx.x;

    __shared__ __align__(16) unsigned vsh[2][32];   // bf16x2 state pairs

    // my two packed exp(T) columns (output states 2*lane, 2*lane+1)
    unsigned eA[32], eB[32];
    {
        const unsigned* ga = g_eTbf + (2 * lane) * 32;
        const unsigned* gb = g_eTbf + (2 * lane + 1) * 32;
#pragma unroll
        for (int k = 0; k < 32; ++k) { eA[k] = ga[k]; eB[k] = gb[k]; }
    }

    const float* emb = em + (size_t)b * (LL * CC);
    const float* mkb = mask + (size_t)b * LL;
    const float2* emb2 = reinterpret_cast<const float2*>(emb) + lane;  // pair (2lane,2lane+1)

    // t = 0
    float v0 = __expf(emb2[0].x + g_trow_start[2 * lane]);
    float v1 = __expf(emb2[0].y + g_trow_start[2 * lane + 1]);
    float S = 0.0f, mx = 0.0f;
    vsh[0][lane] = bfpack(v0, v1);

    // prefetch pipeline, distance 3 (emission pairs + mask)
    float2 ea = emb2[1 * 32], eb = emb2[2 * 32], ec = emb2[3 * 32];
    float  ma = mkb[1],       mb = mkb[2],       mc = mkb[3];

    __syncwarp();

    int cur = 0;
#define ADVANCE(t_)                                                     \
    {                                                                   \
        int ti = (t_) + 3; if (ti > LL - 1) ti = LL - 1;                \
        float2 en = emb2[(size_t)ti * 32];                              \
        float  mn = mkb[ti];                                            \
        ea = eb; ma = mb; eb = ec; mb = mc; ec = en; mc = mn;           \
    }

#pragma unroll 1
    for (int t = 1; t <= LL - 4; t += 4) {
        float2 e0 = ea; float m0 = ma; ADVANCE(t);
        do_step<1>(e0, m0, v0, v1, S, mx, cur, vsh, eA, eB, lane);
        e0 = ea; m0 = ma; ADVANCE(t + 1);
        do_step<2>(e0, m0, v0, v1, S, mx, cur, vsh, eA, eB, lane);
        e0 = ea; m0 = ma; ADVANCE(t + 2);
        do_step<0>(e0, m0, v0, v1, S, mx, cur, vsh, eA, eB, lane);
        e0 = ea; m0 = ma; ADVANCE(t + 3);
        do_step<0>(e0, m0, v0, v1, S, mx, cur, vsh, eA, eB, lane);
    }
    // tail: t = 2045, 2046, 2047
#pragma unroll 1
    for (int t = LL - 3; t < LL; ++t) {
        float2 e0 = ea; float m0 = ma; ADVANCE(t);
        do_step<0>(e0, m0, v0, v1, S, mx, cur, vsh, eA, eB, lane);
    }
#undef ADVANCE

    // partition_b = log( sum_c v[c] * exp(T[c,STOP]) ) + S   (fp32, in-warp)
    float term = v0 * g_eTstop[2 * lane] + v1 * g_eTstop[2 * lane + 1];
#pragma unroll
    for (int o = 16; o; o >>= 1) term += __shfl_xor_sync(0xffffffffu, term, o);
    if (lane == 0) g_part[b] = __logf(term) + S;
}

// ---------------------------------------------------------------------------
// Gold path score per batch (cheap gathers) — exact fp32.
// ---------------------------------------------------------------------------
__global__ void __launch_bounds__(256) scores_kernel(const float* __restrict__ em,
                                                     const float* __restrict__ T,
                                                     const float* __restrict__ mask,
                                                     const int* __restrict__ tags) {
    const int b   = blockIdx.x;
    const int tid = threadIdx.x;
    const float* emb = em + (size_t)b * (LL * CC);
    const float* mkb = mask + (size_t)b * LL;
    const int*   tgb = tags + (size_t)b * LL;

    float acc = 0.f, msum = 0.f;
    for (int t = tid; t < LL; t += 256) {
        msum += mkb[t];
        if (t >= 1) {
            int tg = tgb[t];
            int tq = tgb[t - 1];
            acc += (emb[(size_t)t * CC + tg] + T[tq * CC + tg]) * mkb[t];
        }
    }

    __shared__ float sacc[8], smsum[8];
#pragma unroll
    for (int o = 16; o; o >>= 1) {
        acc  += __shfl_xor_sync(0xffffffffu, acc, o);
        msum += __shfl_xor_sync(0xffffffffu, msum, o);
    }
    int lane = tid & 31, w = tid >> 5;
    if (lane == 0) { sacc[w] = acc; smsum[w] = msum; }
    __syncthreads();
    if (tid == 0) {
        float A = 0.f, M = 0.f;
#pragma unroll
        for (int i = 0; i < 8; ++i) { A += sacc[i]; M += smsum[i]; }
        int t0 = tgb[0];
        float s = A + emb[t0] + T[START_S * CC + t0];
        int last = (int)M - 1;               // mask sum of 1.0s is exact in fp32
        s += T[tgb[last] * CC + STOP_S];
        g_scores[b] = s;
    }
}

// ---------------------------------------------------------------------------
// mean(partition - scores)
// ---------------------------------------------------------------------------
__global__ void __launch_bounds__(512) finalize_kernel(float* __restrict__ out) {
    int tid = threadIdx.x;
    float d = g_part[tid] - g_scores[tid];
    __shared__ float sh[16];
#pragma unroll
    for (int o = 16; o; o >>= 1) d += __shfl_xor_sync(0xffffffffu, d, o);
    if ((tid & 31) == 0) sh[tid >> 5] = d;
    __syncthreads();
    if (tid < 16) {
        float x = sh[tid];
#pragma unroll
        for (int o = 8; o; o >>= 1) x += __shfl_xor_sync(0x0000ffffu, x, o);
        if (tid == 0) out[0] = x * (1.0f / BB);
    }
}

extern "C" void kernel_launch(void* const* d_in, const int* in_sizes, int n_in,
                              void* d_out, int out_size) {
    (void)in_sizes; (void)n_in; (void)out_size;
    const float* em   = (const float*)d_in[0];
    const float* T    = (const float*)d_in[1];
    const float* mask = (const float*)d_in[2];
    const int*   tags = (const int*)d_in[3];
    float* out = (float*)d_out;

    prep_kernel<<<4, 512>>>(T);
    alpha_kernel<<<BB, 32>>>(em, mask);
    scores_kernel<<<BB, 256>>>(em, T, mask, tags);
    finalize_kernel<<<1, 512>>>(out);
}

// round 10
// speedup vs baseline: 2.3191x; 1.4835x over previous
#include <cuda_runtime.h>
#include <cuda_bf16.h>

#define BB 512
#define LL 2048
#define CC 64
#define START_S 62
#define STOP_S 63
#define MID 1023

// scratch (no cudaMalloc allowed)
__device__ unsigned g_eTbfF[CC * 32]; // fwd:  [cp][k2] = bf16x2{exp(T[2k2][cp]),   exp(T[2k2+1][cp])}
__device__ unsigned g_eTbfB[CC * 32]; // bwd:  [c][k2]  = bf16x2{exp(T[c][2k2]),    exp(T[c][2k2+1])}
__device__ float g_eTstop[CC];        // exp(T[c][STOP])
__device__ float g_trow_start[CC];    // T[START][c]
__device__ float g_part[BB];
__device__ float g_scores[BB];

// bf16x2 packed ops
__device__ __forceinline__ unsigned bffma(unsigned a, unsigned b, unsigned c) {
    unsigned d;
    asm("fma.rn.bf16x2 %0, %1, %2, %3;" : "=r"(d) : "r"(a), "r"(b), "r"(c));
    return d;
}
__device__ __forceinline__ unsigned bfadd(unsigned a, unsigned b) {
    unsigned d;
    asm("add.rn.bf16x2 %0, %1, %2;" : "=r"(d) : "r"(a), "r"(b));
    return d;
}
__device__ __forceinline__ float bfsum(unsigned ab) {
    float lo = __uint_as_float(ab << 16);
    float hi = __uint_as_float(ab & 0xffff0000u);
    return lo + hi;
}
__device__ __forceinline__ unsigned bfpack(float x, float y) {
    unsigned d;
    asm("cvt.rn.bf16x2.f32 %0, %1, %2;" : "=r"(d) : "f"(y), "f"(x));
    return d;
}

// ---------------------------------------------------------------------------
// Precompute both packed exp(T) tables + boundary vectors.
// ---------------------------------------------------------------------------
__global__ void prep_kernel(const float* __restrict__ T) {
    int i = blockIdx.x * blockDim.x + threadIdx.x;
    if (i < CC * 32) {
        int c  = i >> 5;
        int k2 = i & 31;
        __nv_bfloat162 pf = __floats2bfloat162_rn(__expf(T[(2 * k2) * CC + c]),
                                                  __expf(T[(2 * k2 + 1) * CC + c]));
        g_eTbfF[i] = *reinterpret_cast<unsigned*>(&pf);
        __nv_bfloat162 pb = __floats2bfloat162_rn(__expf(T[c * CC + 2 * k2]),
                                                  __expf(T[c * CC + 2 * k2 + 1]));
        g_eTbfB[i] = *reinterpret_cast<unsigned*>(&pb);
    }
    if (i < CC) {
        g_eTstop[i]     = __expf(T[i * CC + STOP_S]);
        g_trow_start[i] = T[START_S * CC + i];
    }
}

// two interleaved 64-dots in bf16x2 (this lane's two output states)
__device__ __forceinline__ void dot2(const unsigned* __restrict__ vsh32,
                                     const unsigned* __restrict__ eA,
                                     const unsigned* __restrict__ eB,
                                     float& ra, float& rb) {
    const uint4* q = reinterpret_cast<const uint4*>(vsh32);
    unsigned a0 = 0, a1 = 0, a2 = 0, a3 = 0;
    unsigned b0 = 0, b1 = 0, b2 = 0, b3 = 0;
#pragma unroll
    for (int j = 0; j < 8; ++j) {
        uint4 x = q[j];
        a0 = bffma(x.x, eA[4 * j + 0], a0);
        b0 = bffma(x.x, eB[4 * j + 0], b0);
        a1 = bffma(x.y, eA[4 * j + 1], a1);
        b1 = bffma(x.y, eB[4 * j + 1], b1);
        a2 = bffma(x.z, eA[4 * j + 2], a2);
        b2 = bffma(x.z, eB[4 * j + 2], b2);
        a3 = bffma(x.w, eA[4 * j + 3], a3);
        b3 = bffma(x.w, eB[4 * j + 3], b3);
    }
    ra = bfsum(bfadd(bfadd(a0, a1), bfadd(a2, a3)));
    rb = bfsum(bfadd(bfadd(b0, b1), bfadd(b2, b3)));
}

// forward step: v' = (e_t ⊙ (expT^T v)) ; MODE: 0 plain, 1 launch max, 2 renorm
template <int MODE>
__device__ __forceinline__ void stepF(float2 ev, float mkv,
                                      float& v0, float& v1, float& S, float& mx,
                                      int& cur, unsigned (*vsh)[32],
                                      const unsigned* __restrict__ eA,
                                      const unsigned* __restrict__ eB,
                                      int lane) {
    if (MODE == 1) {
        float x = fmaxf(v0, v1);
#pragma unroll
        for (int o = 16; o; o >>= 1) x = fmaxf(x, __shfl_xor_sync(0xffffffffu, x, o));
        mx = x;
    }
    float ee0 = __expf(ev.x);
    float ee1 = __expf(ev.y);
    float vr0 = v0, vr1 = v1;
    if (MODE == 2) {
        float r = __fdividef(1.0f, mx);
        S += __logf(mx);
        ee0 *= r; vr0 = v0 * r;
        ee1 *= r; vr1 = v1 * r;
    }
    float a, bq;
    dot2(vsh[cur], eA, eB, a, bq);
    float nv0 = (mkv > 0.f) ? a  * ee0 : vr0;
    float nv1 = (mkv > 0.f) ? bq * ee1 : vr1;
    v0 = nv0; v1 = nv1;
    vsh[cur ^ 1][lane] = bfpack(nv0, nv1);
    __syncwarp();
    cur ^= 1;
}

// backward step: w' = expT (e_{t+1} ⊙ w) ; emission applied BEFORE the dot
template <int MODE>
__device__ __forceinline__ void stepB(float2 ev, float mkv,
                                      float& v0, float& v1, float& S, float& mx,
                                      int& cur, unsigned (*vsh)[32],
                                      const unsigned* __restrict__ eA,
                                      const unsigned* __restrict__ eB,
                                      int lane) {
    if (MODE == 1) {
        float x = fmaxf(v0, v1);
#pragma unroll
        for (int o = 16; o; o >>= 1) x = fmaxf(x, __shfl_xor_sync(0xffffffffu, x, o));
        mx = x;
    }
    float ee0 = __expf(ev.x);
    float ee1 = __expf(ev.y);
    float vr0 = v0, vr1 = v1;
    if (MODE == 2) {
        float r = __fdividef(1.0f, mx);
        S += __logf(mx);
        ee0 *= r; vr0 = v0 * r;
        ee1 *= r; vr1 = v1 * r;
    }
    int nxt = cur ^ 1;
    vsh[nxt][lane] = bfpack(v0 * ee0, v1 * ee1);   // u = e⊙w (renorm folded in ee)
    __syncwarp();
    float a, bq;
    dot2(vsh[nxt], eA, eB, a, bq);
    v0 = (mkv > 0.f) ? a  : vr0;
    v1 = (mkv > 0.f) ? bq : vr1;
    cur = nxt;
}

// ---------------------------------------------------------------------------
// Bidirectional forward algorithm in exp-space, bf16 matvec, one batch per
// 64-thread CTA. Warp 0 runs the forward recursion over steps 1..MID; warp 1
// runs the transposed (backward) recursion seeded with exp(T[:,STOP]) over
// steps L-2..MID, consuming emissions t+1. The two 1024-step chains execute
// concurrently — halving the sequential depth — and meet in one dot:
//   logZ = log( sum_c valpha_MID[c] * w_MID[c] ) + S_f + S_b.
// Per warp: lane owns 2 states; exp(T) columns/rows in 64 bf16x2 regs;
// v exchanged via a private 128B bf16x2 buffer with __syncwarp only.
// Renorm every 4 steps, max-shuffle pipelined off the chain.
// ---------------------------------------------------------------------------
__global__ void __launch_bounds__(64) alpha_kernel(const float* __restrict__ em,
                                                   const float* __restrict__ mask) {
    const int b    = blockIdx.x;
    const int lane = threadIdx.x & 31;
    const int wid  = threadIdx.x >> 5;

    __shared__ __align__(16) unsigned vshbuf[2][2][32];  // [warp][buf][lane]
    __shared__ float warr[CC];
    __shared__ float sSb;

    const float* emb = em + (size_t)b * (LL * CC);
    const float* mkb = mask + (size_t)b * LL;
    const float2* emb2 = reinterpret_cast<const float2*>(emb) + lane;

    unsigned (*vsh)[32] = vshbuf[wid];

    float v0, v1, S = 0.0f, mx = 0.0f;

    if (wid == 0) {
        // ---------------- forward half: steps 1..MID ----------------
        unsigned eA[32], eB[32];
        {
            const unsigned* ga = g_eTbfF + (2 * lane) * 32;
            const unsigned* gb = g_eTbfF + (2 * lane + 1) * 32;
#pragma unroll
            for (int k = 0; k < 32; ++k) { eA[k] = ga[k]; eB[k] = gb[k]; }
        }
        v0 = __expf(emb2[0].x + g_trow_start[2 * lane]);
        v1 = __expf(emb2[0].y + g_trow_start[2 * lane + 1]);
        vsh[0][lane] = bfpack(v0, v1);

        float2 ea = emb2[1 * 32], eb = emb2[2 * 32], ec = emb2[3 * 32];
        float  ma = mkb[1],       mb = mkb[2],       mc = mkb[3];
        __syncwarp();

        int cur = 0;
#define ADVF(t_)                                                        \
        {                                                               \
            int ti = (t_) + 3; if (ti > MID) ti = MID;                  \
            float2 en = emb2[(size_t)ti * 32];                          \
            float  mn = mkb[ti];                                        \
            ea = eb; ma = mb; eb = ec; mb = mc; ec = en; mc = mn;       \
        }
#pragma unroll 1
        for (int t = 1; t <= MID - 3; t += 4) {
            float2 e0 = ea; float m0 = ma; ADVF(t);
            stepF<1>(e0, m0, v0, v1, S, mx, cur, vsh, eA, eB, lane);
            e0 = ea; m0 = ma; ADVF(t + 1);
            stepF<2>(e0, m0, v0, v1, S, mx, cur, vsh, eA, eB, lane);
            e0 = ea; m0 = ma; ADVF(t + 2);
            stepF<0>(e0, m0, v0, v1, S, mx, cur, vsh, eA, eB, lane);
            e0 = ea; m0 = ma; ADVF(t + 3);
            stepF<0>(e0, m0, v0, v1, S, mx, cur, vsh, eA, eB, lane);
        }
        // tail: steps MID-2, MID-1, MID  (1020 done above)
#pragma unroll 1
        for (int t = MID - 2; t <= MID; ++t) {
            float2 e0 = ea; float m0 = ma; ADVF(t);
            stepF<0>(e0, m0, v0, v1, S, mx, cur, vsh, eA, eB, lane);
        }
#undef ADVF
    } else {
        // ---------------- backward half: steps L-2 .. MID ----------------
        unsigned eA[32], eB[32];
        {
            const unsigned* ga = g_eTbfB + (2 * lane) * 32;
            const unsigned* gb = g_eTbfB + (2 * lane + 1) * 32;
#pragma unroll
            for (int k = 0; k < 32; ++k) { eA[k] = ga[k]; eB[k] = gb[k]; }
        }
        v0 = g_eTstop[2 * lane];
        v1 = g_eTstop[2 * lane + 1];

        float2 ea = emb2[(size_t)(LL - 1) * 32];
        float2 eb = emb2[(size_t)(LL - 2) * 32];
        float2 ec = emb2[(size_t)(LL - 3) * 32];
        float  ma = mkb[LL - 1], mb = mkb[LL - 2], mc = mkb[LL - 3];
        __syncwarp();

        int cur = 0;
#define ADVB(t_)                                                        \
        {                                                               \
            int ti = (t_) - 2; if (ti < 0) ti = 0;                      \
            float2 en = emb2[(size_t)ti * 32];                          \
            float  mn = mkb[ti];                                        \
            ea = eb; ma = mb; eb = ec; mb = mc; ec = en; mc = mn;       \
        }
        // 1024 steps: t = LL-2 down to MID, exactly 256 quads
#pragma unroll 1
        for (int t = LL - 2; t > MID; t -= 4) {
            float2 e0 = ea; float m0 = ma; ADVB(t);
            stepB<1>(e0, m0, v0, v1, S, mx, cur, vsh, eA, eB, lane);
            e0 = ea; m0 = ma; ADVB(t - 1);
            stepB<2>(e0, m0, v0, v1, S, mx, cur, vsh, eA, eB, lane);
            e0 = ea; m0 = ma; ADVB(t - 2);
            stepB<0>(e0, m0, v0, v1, S, mx, cur, vsh, eA, eB, lane);
            e0 = ea; m0 = ma; ADVB(t - 3);
            stepB<0>(e0, m0, v0, v1, S, mx, cur, vsh, eA, eB, lane);
        }
#undef ADVB
        warr[2 * lane]     = v0;
        warr[2 * lane + 1] = v1;
        if (lane == 0) sSb = S;
    }

    __syncthreads();

    if (wid == 0) {
        // logZ = log( sum_c valpha[c] * w[c] ) + S_f + S_b
        float term = v0 * warr[2 * lane] + v1 * warr[2 * lane + 1];
#pragma unroll
        for (int o = 16; o; o >>= 1) term += __shfl_xor_sync(0xffffffffu, term, o);
        if (lane == 0) g_part[b] = __logf(term) + S + sSb;
    }
}

// ---------------------------------------------------------------------------
// Gold path score per batch (cheap gathers) — exact fp32.
// ---------------------------------------------------------------------------
__global__ void __launch_bounds__(256) scores_kernel(const float* __restrict__ em,
                                                     const float* __restrict__ T,
                                                     const float* __restrict__ mask,
                                                     const int* __restrict__ tags) {
    const int b   = blockIdx.x;
    const int tid = threadIdx.x;
    const float* emb = em + (size_t)b * (LL * CC);
    const float* mkb = mask + (size_t)b * LL;
    const int*   tgb = tags + (size_t)b * LL;

    float acc = 0.f, msum = 0.f;
    for (int t = tid; t < LL; t += 256) {
        msum += mkb[t];
        if (t >= 1) {
            int tg = tgb[t];
            int tq = tgb[t - 1];
            acc += (emb[(size_t)t * CC + tg] + T[tq * CC + tg]) * mkb[t];
        }
    }

    __shared__ float sacc[8], smsum[8];
#pragma unroll
    for (int o = 16; o; o >>= 1) {
        acc  += __shfl_xor_sync(0xffffffffu, acc, o);
        msum += __shfl_xor_sync(0xffffffffu, msum, o);
    }
    int lane = tid & 31, w = tid >> 5;
    if (lane == 0) { sacc[w] = acc; smsum[w] = msum; }
    __syncthreads();
    if (tid == 0) {
        float A = 0.f, M = 0.f;
#pragma unroll
        for (int i = 0; i < 8; ++i) { A += sacc[i]; M += smsum[i]; }
        int t0 = tgb[0];
        float s = A + emb[t0] + T[START_S * CC + t0];
        int last = (int)M - 1;               // mask sum of 1.0s is exact in fp32
        s += T[tgb[last] * CC + STOP_S];
        g_scores[b] = s;
    }
}

// ---------------------------------------------------------------------------
// mean(partition - scores)
// ---------------------------------------------------------------------------
__global__ void __launch_bounds__(512) finalize_kernel(float* __restrict__ out) {
    int tid = threadIdx.x;
    float d = g_part[tid] - g_scores[tid];
    __shared__ float sh[16];
#pragma unroll
    for (int o = 16; o; o >>= 1) d += __shfl_xor_sync(0xffffffffu, d, o);
    if ((tid & 31) == 0) sh[tid >> 5] = d;
    __syncthreads();
    if (tid < 16) {
        float x = sh[tid];
#pragma unroll
        for (int o = 8; o; o >>= 1) x += __shfl_xor_sync(0x0000ffffu, x, o);
        if (tid == 0) out[0] = x * (1.0f / BB);
    }
}

extern "C" void kernel_launch(void* const* d_in, const int* in_sizes, int n_in,
                              void* d_out, int out_size) {
    (void)in_sizes; (void)n_in; (void)out_size;
    const float* em   = (const float*)d_in[0];
    const float* T    = (const float*)d_in[1];
    const float* mask = (const float*)d_in[2];
    const int*   tags = (const int*)d_in[3];
    float* out = (float*)d_out;

    prep_kernel<<<4, 512>>>(T);
    alpha_kernel<<<BB, 64>>>(em, mask);
    scores_kernel<<<BB, 256>>>(em, T, mask, tags);
    finalize_kernel<<<1, 512>>>(out);
}